// round 10
// baseline (speedup 1.0000x reference)
#include <cuda_runtime.h>
#include <cstdint>

#define BATCH 256
#define DIM   2048
#define PNUM  56
#define CH    8                        // column chunks per batch row
#define C4    64                       // float4 per chunk (256 floats)
#define RPAD  260                      // padded row length in floats (65 x 16B)
#define GRID1 (BATCH * CH)             // 2048

// smem layout (floats)
#define S_P    0                       // 56 x 260
#define S_M    (56 * RPAD)             // 14560: mean, 256 floats
#define S_MG   (S_M + 256)             // 14816: m - g, 256 floats
#define S_RED  (S_MG + 256)            // 15072: 1024 floats (mean/dcl partials, finalize)
#define SMEMF  (S_RED + 1024)          // 16096 floats = 64384 bytes

#define KEXP  0.3606737602222409f

typedef unsigned long long u64;

// --- device scratch (static zero-init; kernel self-resets before exit) ---
__device__ double       g_acc0;                 // dil
__device__ double       g_acc1;                 // dcl
__device__ unsigned int g_done;                 // finalizer count
__device__ unsigned int g_cntb[BATCH];          // per-b chunk-completion count
__device__ float4       scr_dcl[GRID1 * 56];    // per (b,ch): 56 row partials
__device__ float4       scr_dil[GRID1 * 2];     // per (b,ch): 2 warp partials

__device__ __forceinline__ float ex2f(float x) {
    float r; asm("ex2.approx.ftz.f32 %0, %1;" : "=f"(r) : "f"(x)); return r;
}
__device__ __forceinline__ u64 f2_add(u64 a, u64 b) {
    u64 r; asm("add.rn.f32x2 %0, %1, %2;" : "=l"(r) : "l"(a), "l"(b)); return r;
}
__device__ __forceinline__ u64 f2_mul(u64 a, u64 b) {
    u64 r; asm("mul.rn.f32x2 %0, %1, %2;" : "=l"(r) : "l"(a), "l"(b)); return r;
}
__device__ __forceinline__ u64 f2_fma(u64 a, u64 b, u64 c) {
    u64 r; asm("fma.rn.f32x2 %0, %1, %2, %3;" : "=l"(r) : "l"(a), "l"(b), "l"(c)); return r;
}
__device__ __forceinline__ void f2_unpack(u64 v, float& lo, float& hi) {
    asm("mov.b64 {%0, %1}, %2;" : "=f"(lo), "=f"(hi) : "l"(v));
}
__device__ __forceinline__ u64 f2_pack(float lo, float hi) {
    u64 r; asm("mov.b64 %0, {%1, %2};" : "=l"(r) : "f"(lo), "f"(hi)); return r;
}
// volatile v4 load (ld.global.cv) for cross-block scratch readback
__device__ __forceinline__ float4 ld_cv4(const float4* p) {
    float4 v;
    asm volatile("ld.global.cv.v4.f32 {%0,%1,%2,%3}, [%4];"
                 : "=f"(v.x), "=f"(v.y), "=f"(v.z), "=f"(v.w) : "l"(p));
    return v;
}

#define F2_NEG1 0xBF800000BF800000ULL
#define F2_KK   0x3EB8AA3B3EB8AA3BULL   /* (KEXP, KEXP) */
#define F2_I56  0x3C9249253C924925ULL   /* (1/56, 1/56) */

// ============================================================================
// k1: single pass over ebp. Block = (b, chunk).
// A: load 56 rows -> smem, mean in-flight. Mid: m, mg, dil partials.
// C: thread=(row,subchunk) dcl partials -> smem; fold -> 56 float4 -> scratch.
// Tail: 8th block of each b finalizes that b; 256th finalizer writes out and
// resets all global state to zero (graph-replay safe).
// ============================================================================
__global__ void __launch_bounds__(256, 3) k1(const float* __restrict__ ebp,
                                             const float* __restrict__ ebg,
                                             float* __restrict__ out) {
    extern __shared__ float sm[];
    __shared__ int s_fin, s_out;
    int b  = blockIdx.x >> 3;
    int ch = blockIdx.x & 7;
    int tid = threadIdx.x;

    // ---- Phase A: load + mean ----
    int rg = tid >> 6;          // row group 0..3
    int c4 = tid & 63;          // float4 index within chunk
    const ulonglong2* eb = (const ulonglong2*)ebp;
    size_t coff = (size_t)ch * C4 + c4;
    u64 aLo = 0, aHi = 0;
#pragma unroll 14
    for (int i = 0; i < 14; i++) {
        int p = i * 4 + rg;
        ulonglong2 v = eb[(size_t)(p * BATCH + b) * 512 + coff];
        *(ulonglong2*)&sm[S_P + p * RPAD + c4 * 4] = v;
        aLo = f2_add(aLo, v.x);
        aHi = f2_add(aHi, v.y);
    }
    *(ulonglong2*)&sm[S_RED + rg * 256 + c4 * 4] = make_ulonglong2(aLo, aHi);
    __syncthreads();

    // ---- Mid: finalize mean, mg, dil partials (threads 0..63) ----
    if (tid < 64) {
        ulonglong2 r0 = *(ulonglong2*)&sm[S_RED + 0 * 256 + tid * 4];
        ulonglong2 r1 = *(ulonglong2*)&sm[S_RED + 1 * 256 + tid * 4];
        ulonglong2 r2 = *(ulonglong2*)&sm[S_RED + 2 * 256 + tid * 4];
        ulonglong2 r3 = *(ulonglong2*)&sm[S_RED + 3 * 256 + tid * 4];
        u64 mLo = f2_mul(f2_add(f2_add(r0.x, r1.x), f2_add(r2.x, r3.x)), F2_I56);
        u64 mHi = f2_mul(f2_add(f2_add(r0.y, r1.y), f2_add(r2.y, r3.y)), F2_I56);
        ulonglong2 g = ((const ulonglong2*)ebg)[(size_t)b * 512 + coff];
        u64 mgLo = f2_fma(g.x, F2_NEG1, mLo);
        u64 mgHi = f2_fma(g.y, F2_NEG1, mHi);
        *(ulonglong2*)&sm[S_M  + tid * 4] = make_ulonglong2(mLo, mHi);
        *(ulonglong2*)&sm[S_MG + tid * 4] = make_ulonglong2(mgLo, mgHi);

        float m0, m1, m2, m3, g0, g1, g2, g3, u0, u1, u2, u3;
        f2_unpack(mLo, m0, m1); f2_unpack(mHi, m2, m3);
        f2_unpack(g.x, g0, g1); f2_unpack(g.y, g2, g3);
        f2_unpack(mgLo, u0, u1); f2_unpack(mgHi, u2, u3);
        float se_g = 0.f, se_m = 0.f, su_g = 0.f, su_m = 0.f;
#define DIL1(gg, mm, uu) { float eg = ex2f(gg * KEXP);          \
                           float em = ex2f(mm * KEXP);          \
                           se_g += eg; se_m += em;              \
                           su_g = fmaf(eg, uu, su_g);           \
                           su_m = fmaf(em, uu, su_m); }
        DIL1(g0, m0, u0) DIL1(g1, m1, u1) DIL1(g2, m2, u2) DIL1(g3, m3, u3)
#undef DIL1
#pragma unroll
        for (int off = 16; off; off >>= 1) {
            se_g += __shfl_xor_sync(0xffffffffu, se_g, off);
            se_m += __shfl_xor_sync(0xffffffffu, se_m, off);
            su_g += __shfl_xor_sync(0xffffffffu, su_g, off);
            su_m += __shfl_xor_sync(0xffffffffu, su_m, off);
        }
        if ((tid & 31) == 0)
            scr_dil[blockIdx.x * 2 + (tid >> 5)] =
                make_float4(se_g, se_m, su_g, su_m);
    }
    __syncthreads();

    // ---- Phase C: per-thread dcl partials -> smem ----
    int s = tid / 56;                  // subchunk 0..3 (tid>=224 idle)
    int r = tid - s * 56;              // row 0..55
    if (s < 4) {
        int j0 = s * 16;
        u64 seX = 0, seY = 0, suX = 0, suY = 0;
#pragma unroll 16
        for (int j = 0; j < 16; j++) {
            ulonglong2 P  = *(ulonglong2*)&sm[S_P  + r * RPAD + (j0 + j) * 4];
            ulonglong2 M  = *(ulonglong2*)&sm[S_M  + (j0 + j) * 4];
            ulonglong2 MG = *(ulonglong2*)&sm[S_MG + (j0 + j) * 4];
#define DCLP(pp, mm, gm) {                                       \
            u64 db = f2_fma(pp, F2_NEG1, mm);    /* m - p */     \
            u64 dg = f2_fma(gm, F2_NEG1, db);    /* g - p */     \
            u64 w  = f2_add(db, dg);                             \
            u64 u  = f2_mul(gm, w);                              \
            u64 ax = f2_mul(f2_mul(dg, dg), F2_KK);              \
            u64 ay = f2_mul(f2_mul(db, db), F2_KK);              \
            float a0, a1, b0, b1;                                \
            f2_unpack(ax, a0, a1); f2_unpack(ay, b0, b1);        \
            u64 ex = f2_pack(ex2f(a0), ex2f(a1));                \
            u64 ey = f2_pack(ex2f(b0), ex2f(b1));                \
            seX = f2_add(seX, ex); seY = f2_add(seY, ey);        \
            suX = f2_fma(ex, u, suX); suY = f2_fma(ey, u, suY); }
            DCLP(P.x, M.x, MG.x)
            DCLP(P.y, M.y, MG.y)
#undef DCLP
        }
        float x0, x1, y0, y1, z0, z1, w0, w1;
        f2_unpack(seX, x0, x1); f2_unpack(seY, y0, y1);
        f2_unpack(suX, z0, z1); f2_unpack(suY, w0, w1);
        *(float4*)&sm[S_RED + (s * 56 + r) * 4] =
            make_float4(x0 + x1, y0 + y1, z0 + z1, w0 + w1);
    }
    __syncthreads();

    // ---- fold 4 subchunks -> 1 float4 per row, write coalesced ----
    if (tid < 56) {
        float4 a = *(float4*)&sm[S_RED + (0 * 56 + tid) * 4];
        float4 c = *(float4*)&sm[S_RED + (1 * 56 + tid) * 4];
        float4 d = *(float4*)&sm[S_RED + (2 * 56 + tid) * 4];
        float4 e = *(float4*)&sm[S_RED + (3 * 56 + tid) * 4];
        scr_dcl[blockIdx.x * 56 + tid] =
            make_float4(a.x + c.x + d.x + e.x, a.y + c.y + d.y + e.y,
                        a.z + c.z + d.z + e.z, a.w + c.w + d.w + e.w);
    }

    // ---- Tail: 8th block of this b finalizes it ----
    __threadfence();
    __syncthreads();
    if (tid == 0)
        s_fin = (atomicAdd(&g_cntb[b], 1u) == CH - 1) ? 1 : 0;
    __syncthreads();
    if (!s_fin) return;

    int lane = tid & 31;
    if (tid < 56) {
        float4 a = make_float4(0.f, 0.f, 0.f, 0.f);
#pragma unroll 8
        for (int cc = 0; cc < CH; cc++) {
            float4 v = ld_cv4(&scr_dcl[(b * CH + cc) * 56 + tid]);
            a.x += v.x; a.y += v.y; a.z += v.z; a.w += v.w;
        }
        sm[S_RED + tid] = a.w / a.y - a.z / a.x;
    }
    if (tid >= 224) {                   // warp 7: dil combine for this b
        float4 v = (lane < 16) ? ld_cv4(&scr_dil[b * 16 + lane])
                               : make_float4(0.f, 0.f, 0.f, 0.f);
#pragma unroll
        for (int off = 8; off; off >>= 1) {
            v.x += __shfl_xor_sync(0xffffffffu, v.x, off);
            v.y += __shfl_xor_sync(0xffffffffu, v.y, off);
            v.z += __shfl_xor_sync(0xffffffffu, v.z, off);
            v.w += __shfl_xor_sync(0xffffffffu, v.w, off);
        }
        if (lane == 0)
            atomicAdd(&g_acc0, (double)(v.w / v.y - v.z / v.x));
    }
    __syncthreads();
    if (tid < 32) {
        float ss = ((lane < 56) ? sm[S_RED + lane] : 0.f) +
                   ((lane + 32 < 56) ? sm[S_RED + lane + 32] : 0.f);
#pragma unroll
        for (int off = 16; off; off >>= 1)
            ss += __shfl_xor_sync(0xffffffffu, ss, off);
        if (lane == 0) atomicAdd(&g_acc1, (double)ss);
    }

    __threadfence();
    __syncthreads();
    if (tid == 0) {
        g_cntb[b] = 0u;                         // self-reset for next replay
        unsigned prev = atomicAdd(&g_done, 1u);
        s_out = (prev == BATCH - 1) ? 1 : 0;
    }
    __syncthreads();
    if (s_out && tid == 0) {
        __threadfence();
        double a0 = *(volatile double*)&g_acc0;
        double a1 = *(volatile double*)&g_acc1;
        out[0] = (float)(a0 * (4.0 / (double)DIM));
        out[1] = (float)(a1 * (4.0 / ((double)DIM * (double)PNUM)));
        *(volatile double*)&g_acc0 = 0.0;       // self-reset
        *(volatile double*)&g_acc1 = 0.0;
        *(volatile unsigned int*)&g_done = 0u;
        __threadfence();
    }
}

extern "C" void kernel_launch(void* const* d_in, const int* in_sizes, int n_in,
                              void* d_out, int out_size) {
    const float* ebg = (const float*)d_in[0];
    const float* ebp = (const float*)d_in[1];
    (void)in_sizes; (void)n_in; (void)out_size;

    cudaFuncSetAttribute(k1, cudaFuncAttributeMaxDynamicSharedMemorySize,
                         SMEMF * sizeof(float));
    k1<<<GRID1, 256, SMEMF * sizeof(float)>>>(ebp, ebg, (float*)d_out);
}